// round 1
// baseline (speedup 1.0000x reference)
#include <cuda_runtime.h>

// NARX RNN: NT=512, NGRID=2048, NX=16, NY=1, HID=64, D=4
// Pass 1: V[s][j][g] = (relu(x[s,g]@W_in + b_in) @ W_xh)[j] + b_h[j]   (s-only, computed once)
// Pass 2: per window r (output t=r+4): h=tanh(V[r]); for d=1..3: h=tanh(V[r+d]+h@W_hh);
//         out[t,g] = h @ W_out + b_out.  out[0:4] = 0.

#define NTT   512
#define NGRID 2048
#define NXF   16
#define HID   64
#define DLY   4
#define TOUT  (NTT - DLY)   // 508

// scratch: 512 * 64 * 2048 floats = 256 MiB
__device__ float g_V[(size_t)NTT * HID * NGRID];

__device__ __forceinline__ float tanh_fast(float v) {
    v = fminf(fmaxf(v, -20.0f), 20.0f);
    float e = __expf(2.0f * v);
    return __fdividef(e - 1.0f, e + 1.0f);
}

__global__ __launch_bounds__(128)
void narx_pass1(const float* __restrict__ x,
                const float* __restrict__ W_in,  // [NX, HID]
                const float* __restrict__ b_in,  // [HID]
                const float* __restrict__ W_xh,  // [HID, HID]
                const float* __restrict__ b_h)   // [HID]
{
    __shared__ float sWinT[HID * NXF];   // transposed: [i][k]
    __shared__ float sWxh[HID * HID];    // row-major [i][j]
    __shared__ float sbin[HID];
    __shared__ float sbh[HID];

    int tid = threadIdx.x;
    for (int p = tid; p < HID * NXF; p += 128) {
        int i = p / NXF, k = p % NXF;
        sWinT[p] = W_in[k * HID + i];
    }
    for (int p = tid; p < HID * HID; p += 128) sWxh[p] = W_xh[p];
    if (tid < HID) { sbin[tid] = b_in[tid]; sbh[tid] = b_h[tid]; }
    __syncthreads();

    int idx = blockIdx.x * 128 + tid;
    int g = idx & (NGRID - 1);
    int s = idx >> 11;               // NGRID = 2048 = 2^11

    // load x[s,g,0..15] (16 consecutive floats, 4x float4)
    const float4* xp = reinterpret_cast<const float4*>(x + ((size_t)s * NGRID + g) * NXF);
    float xv[NXF];
#pragma unroll
    for (int q = 0; q < 4; q++) {
        float4 v = xp[q];
        xv[4*q+0] = v.x; xv[4*q+1] = v.y; xv[4*q+2] = v.z; xv[4*q+3] = v.w;
    }

    float acc[HID];
#pragma unroll
    for (int j = 0; j < HID; j++) acc[j] = sbh[j];

#pragma unroll 4
    for (int i = 0; i < HID; i++) {
        float u = sbin[i];
        const float4* wt = reinterpret_cast<const float4*>(&sWinT[i * NXF]);
#pragma unroll
        for (int q = 0; q < 4; q++) {
            float4 w = wt[q];
            u = fmaf(xv[4*q+0], w.x, u);
            u = fmaf(xv[4*q+1], w.y, u);
            u = fmaf(xv[4*q+2], w.z, u);
            u = fmaf(xv[4*q+3], w.w, u);
        }
        u = fmaxf(u, 0.0f);
        const float4* wr = reinterpret_cast<const float4*>(&sWxh[i * HID]);
#pragma unroll
        for (int q = 0; q < 16; q++) {
            float4 w = wr[q];
            acc[4*q+0] = fmaf(u, w.x, acc[4*q+0]);
            acc[4*q+1] = fmaf(u, w.y, acc[4*q+1]);
            acc[4*q+2] = fmaf(u, w.z, acc[4*q+2]);
            acc[4*q+3] = fmaf(u, w.w, acc[4*q+3]);
        }
    }

    float* vout = g_V + (size_t)s * HID * NGRID + g;
#pragma unroll
    for (int j = 0; j < HID; j++) vout[(size_t)j * NGRID] = acc[j];
}

__global__ __launch_bounds__(128)
void narx_pass2(const float* __restrict__ W_hh,   // [HID, HID]
                const float* __restrict__ W_out,  // [HID, 1]
                const float* __restrict__ b_out,  // [1]
                float* __restrict__ out)          // [NT, NGRID]
{
    __shared__ float sW[HID * HID];
    __shared__ float sWout[HID];

    int tid = threadIdx.x;
    for (int p = tid; p < HID * HID; p += 128) sW[p] = W_hh[p];
    if (tid < HID) sWout[tid] = W_out[tid];
    __syncthreads();

    int idx = blockIdx.x * 128 + tid;
    int g = idx & (NGRID - 1);
    int r = idx >> 11;    // 0..507

    const float* Vbase = g_V + (size_t)r * HID * NGRID + g;

    float h[HID];
#pragma unroll
    for (int j = 0; j < HID; j++) h[j] = tanh_fast(Vbase[(size_t)j * NGRID]);

#pragma unroll 1
    for (int d = 1; d < DLY; d++) {
        const float* Vd = Vbase + (size_t)d * HID * NGRID;
        float acc[HID];
#pragma unroll
        for (int j = 0; j < HID; j++) acc[j] = Vd[(size_t)j * NGRID];
#pragma unroll 4
        for (int i = 0; i < HID; i++) {
            float hi = h[i];
            const float4* wr = reinterpret_cast<const float4*>(&sW[i * HID]);
#pragma unroll
            for (int q = 0; q < 16; q++) {
                float4 w = wr[q];
                acc[4*q+0] = fmaf(hi, w.x, acc[4*q+0]);
                acc[4*q+1] = fmaf(hi, w.y, acc[4*q+1]);
                acc[4*q+2] = fmaf(hi, w.z, acc[4*q+2]);
                acc[4*q+3] = fmaf(hi, w.w, acc[4*q+3]);
            }
        }
#pragma unroll
        for (int j = 0; j < HID; j++) h[j] = tanh_fast(acc[j]);
    }

    float y = b_out[0];
#pragma unroll
    for (int j = 0; j < HID; j++) y = fmaf(h[j], sWout[j], y);

    out[(size_t)(r + DLY) * NGRID + g] = y;
}

__global__ void narx_zero_head(float* __restrict__ out)
{
    int i = blockIdx.x * 256 + threadIdx.x;
    if (i < DLY * NGRID) out[i] = 0.0f;
}

extern "C" void kernel_launch(void* const* d_in, const int* in_sizes, int n_in,
                              void* d_out, int out_size)
{
    const float* x     = (const float*)d_in[0];
    const float* W_in  = (const float*)d_in[1];
    const float* b_in  = (const float*)d_in[2];
    const float* W_xh  = (const float*)d_in[3];
    const float* W_hh  = (const float*)d_in[4];
    const float* b_h   = (const float*)d_in[5];
    const float* W_out = (const float*)d_in[6];
    const float* b_out = (const float*)d_in[7];
    float* out = (float*)d_out;

    (void)in_sizes; (void)n_in; (void)out_size;

    // Pass 1: 512*2048 threads
    narx_pass1<<<(NTT * NGRID) / 128, 128>>>(x, W_in, b_in, W_xh, b_h);
    // Pass 2: 508*2048 threads
    narx_pass2<<<(TOUT * NGRID) / 128, 128>>>(W_hh, W_out, b_out, out);
    // zero rows 0..3
    narx_zero_head<<<(DLY * NGRID + 255) / 256, 256>>>(out);
}

// round 2
// speedup vs baseline: 1.0521x; 1.0521x over previous
#include <cuda_runtime.h>

// NARX RNN: NT=512, NGRID=2048, NX=16, NY=1, HID=64, D=4
// Pass 1: V[s][j][g] = (relu(x[s,g]@W_in + b_in) @ W_xh)[j] + b_h[j]   (s-only, once)
// Pass 2: h=tanh(V[r]); for d=1..3: h=tanh(V[r+d] + h@W_hh); out[r+4,g] = h@W_out + b_out
// All inner products use packed fma.rn.f32x2 (Blackwell FFMA2, 2x fp32 throughput).

#define NTT   512
#define NGRID 2048
#define NXF   16
#define HID   64
#define DLY   4
#define TOUT  (NTT - DLY)   // 508

typedef unsigned long long ull;

// scratch: 512 * 64 * 2048 floats = 256 MiB
__device__ float g_V[(size_t)NTT * HID * NGRID];

__device__ __forceinline__ ull pack2(float lo, float hi) {
    ull r; asm("mov.b64 %0, {%1,%2};" : "=l"(r) : "f"(lo), "f"(hi)); return r;
}
__device__ __forceinline__ void unpack2(ull p, float& lo, float& hi) {
    asm("mov.b64 {%0,%1}, %2;" : "=f"(lo), "=f"(hi) : "l"(p));
}
__device__ __forceinline__ ull fma2(ull a, ull b, ull c) {
    ull d; asm("fma.rn.f32x2 %0, %1, %2, %3;" : "=l"(d) : "l"(a), "l"(b), "l"(c)); return d;
}

__device__ __forceinline__ float tanh_fast(float v) {
    v = fminf(fmaxf(v, -20.0f), 20.0f);
    float e = __expf(2.0f * v);
    return __fdividef(e - 1.0f, e + 1.0f);
}

__global__ __launch_bounds__(128)
void narx_pass1(const float* __restrict__ x,
                const float* __restrict__ W_in,  // [NX, HID]
                const float* __restrict__ b_in,  // [HID]
                const float* __restrict__ W_xh,  // [HID, HID]
                const float* __restrict__ b_h)   // [HID]
{
    __shared__ __align__(16) float sWinT[HID * NXF];   // transposed: [i][k]
    __shared__ __align__(16) float sWxh[HID * HID];    // row-major [i][j]
    __shared__ __align__(16) float sbin[HID];
    __shared__ __align__(16) float sbh[HID];

    int tid = threadIdx.x;
    for (int p = tid; p < HID * NXF; p += 128) {
        int i = p / NXF, k = p % NXF;
        sWinT[p] = W_in[k * HID + i];
    }
    for (int p = tid; p < HID * HID; p += 128) sWxh[p] = W_xh[p];
    if (tid < HID) { sbin[tid] = b_in[tid]; sbh[tid] = b_h[tid]; }
    __syncthreads();

    int idx = blockIdx.x * 128 + tid;
    int g = idx & (NGRID - 1);
    int s = idx >> 11;               // NGRID = 2048 = 2^11

    // load x[s,g,0..15] as 8 packed pairs
    const ulonglong2* xp = reinterpret_cast<const ulonglong2*>(x + ((size_t)s * NGRID + g) * NXF);
    ull xv2[8];
#pragma unroll
    for (int q = 0; q < 4; q++) {
        ulonglong2 t = xp[q];
        xv2[2*q] = t.x; xv2[2*q+1] = t.y;
    }

    ull acc2[HID/2];
    {
        const ull* bh2 = reinterpret_cast<const ull*>(sbh);
#pragma unroll
        for (int p = 0; p < HID/2; p++) acc2[p] = bh2[p];
    }

#pragma unroll 4
    for (int i = 0; i < HID; i++) {
        // u = relu(b_in[i] + sum_k x[k]*WinT[i][k]) via packed dot
        ull u2 = pack2(sbin[i], 0.0f);
        const ulonglong2* wt = reinterpret_cast<const ulonglong2*>(&sWinT[i * NXF]);
#pragma unroll
        for (int q = 0; q < 4; q++) {
            ulonglong2 w = wt[q];
            u2 = fma2(xv2[2*q],   w.x, u2);
            u2 = fma2(xv2[2*q+1], w.y, u2);
        }
        float ulo, uhi; unpack2(u2, ulo, uhi);
        float u = fmaxf(ulo + uhi, 0.0f);
        ull uu = pack2(u, u);

        const ulonglong2* wr = reinterpret_cast<const ulonglong2*>(&sWxh[i * HID]);
#pragma unroll
        for (int q = 0; q < HID/4; q++) {
            ulonglong2 w = wr[q];
            acc2[2*q]   = fma2(uu, w.x, acc2[2*q]);
            acc2[2*q+1] = fma2(uu, w.y, acc2[2*q+1]);
        }
    }

    float* vout = g_V + (size_t)s * HID * NGRID + g;
#pragma unroll
    for (int p = 0; p < HID/2; p++) {
        float a, b; unpack2(acc2[p], a, b);
        vout[(size_t)(2*p)   * NGRID] = a;
        vout[(size_t)(2*p+1) * NGRID] = b;
    }
}

__global__ __launch_bounds__(128)
void narx_pass2(const float* __restrict__ W_hh,   // [HID, HID]
                const float* __restrict__ W_out,  // [HID, 1]
                const float* __restrict__ b_out,  // [1]
                float* __restrict__ out)          // [NT, NGRID]
{
    __shared__ __align__(16) float sW[HID * HID];
    __shared__ __align__(16) float sWout[HID];

    int tid = threadIdx.x;
    for (int p = tid; p < HID * HID; p += 128) sW[p] = W_hh[p];
    if (tid < HID) sWout[tid] = W_out[tid];
    __syncthreads();

    int idx = blockIdx.x * 128 + tid;
    int g = idx & (NGRID - 1);
    int r = idx >> 11;    // 0..507

    const float* Vbase = g_V + (size_t)r * HID * NGRID + g;

    float h[HID];
#pragma unroll
    for (int j = 0; j < HID; j++) h[j] = tanh_fast(Vbase[(size_t)j * NGRID]);

#pragma unroll 1
    for (int d = 1; d < DLY; d++) {
        const float* Vd = Vbase + (size_t)d * HID * NGRID;
        ull acc2[HID/2];
#pragma unroll
        for (int p = 0; p < HID/2; p++)
            acc2[p] = pack2(Vd[(size_t)(2*p) * NGRID], Vd[(size_t)(2*p+1) * NGRID]);

#pragma unroll 4
        for (int i = 0; i < HID; i++) {
            ull hh = pack2(h[i], h[i]);
            const ulonglong2* wr = reinterpret_cast<const ulonglong2*>(&sW[i * HID]);
#pragma unroll
            for (int q = 0; q < HID/4; q++) {
                ulonglong2 w = wr[q];
                acc2[2*q]   = fma2(hh, w.x, acc2[2*q]);
                acc2[2*q+1] = fma2(hh, w.y, acc2[2*q+1]);
            }
        }
#pragma unroll
        for (int p = 0; p < HID/2; p++) {
            float a, b; unpack2(acc2[p], a, b);
            h[2*p]   = tanh_fast(a);
            h[2*p+1] = tanh_fast(b);
        }
    }

    float y = b_out[0];
#pragma unroll
    for (int j = 0; j < HID; j++) y = fmaf(h[j], sWout[j], y);

    out[(size_t)(r + DLY) * NGRID + g] = y;
}

__global__ void narx_zero_head(float* __restrict__ out)
{
    int i = blockIdx.x * 256 + threadIdx.x;
    if (i < DLY * NGRID) out[i] = 0.0f;
}

extern "C" void kernel_launch(void* const* d_in, const int* in_sizes, int n_in,
                              void* d_out, int out_size)
{
    const float* x     = (const float*)d_in[0];
    const float* W_in  = (const float*)d_in[1];
    const float* b_in  = (const float*)d_in[2];
    const float* W_xh  = (const float*)d_in[3];
    const float* W_hh  = (const float*)d_in[4];
    const float* b_h   = (const float*)d_in[5];
    const float* W_out = (const float*)d_in[6];
    const float* b_out = (const float*)d_in[7];
    float* out = (float*)d_out;

    (void)in_sizes; (void)n_in; (void)out_size;

    narx_pass1<<<(NTT * NGRID) / 128, 128>>>(x, W_in, b_in, W_xh, b_h);
    narx_pass2<<<(TOUT * NGRID) / 128, 128>>>(W_hh, W_out, b_out, out);
    narx_zero_head<<<(DLY * NGRID + 255) / 256, 256>>>(out);
}